// round 9
// baseline (speedup 1.0000x reference)
#include <cuda_runtime.h>

// ---------------------------------------------------------------------------
// MSELoss: out[0] = mean((yhat - y)^2) over 16384 x 4096 fp32 (512 MiB read).
// R9: finer CTA granularity — 8192 CTAs x 256 thr. Same plain compiler-
// scheduled float4 grid-stride body (the 85% DRAM proven shape). Mechanism:
// T_chip tail cost ~ T_CTA * spread; shorter CTAs shrink the absolute
// last-wave tail (data trend: 2048 short >= 1184 long >= 1024 long CTAs).
// Fused deterministic last-block-done finalization, self-resetting counter.
//
// Rejected with evidence: manual unroll (90.1us), __ldcs (83.4us),
// 1024x256 (imbalance), 1184 full wave (neutral), 1024x512 (neutral).
// ---------------------------------------------------------------------------

#define NBLK 8192
#define NTHR 256

__device__ float        g_partials[NBLK];
__device__ unsigned int g_done_count = 0;

__device__ __forceinline__ float block_reduce(float acc, float* warp_sums)
{
    #pragma unroll
    for (int off = 16; off > 0; off >>= 1)
        acc += __shfl_xor_sync(0xFFFFFFFFu, acc, off);

    int lane = threadIdx.x & 31;
    int wid  = threadIdx.x >> 5;
    if (lane == 0) warp_sums[wid] = acc;
    __syncthreads();

    float v = 0.0f;
    if (wid == 0) {
        v = (lane < NTHR / 32) ? warp_sums[lane] : 0.0f;
        #pragma unroll
        for (int off = 16; off > 0; off >>= 1)
            v += __shfl_xor_sync(0xFFFFFFFFu, v, off);
    }
    return v;  // valid in warp 0 lane 0
}

__global__ __launch_bounds__(NTHR) void mse_kernel(
    const float* __restrict__ yhat,
    const float* __restrict__ y,
    float* __restrict__ out,
    long long n4, float inv_n)
{
    const float4* __restrict__ a4 = reinterpret_cast<const float4*>(yhat);
    const float4* __restrict__ b4 = reinterpret_cast<const float4*>(y);

    // Plain grid-stride loop, compiler-scheduled (best-measured shape).
    // stride = 8192*256 = 2097152; each thread: 8 float4 iterations.
    float acc = 0.0f;
    long long stride = (long long)gridDim.x * blockDim.x;
    for (long long i = (long long)blockIdx.x * blockDim.x + threadIdx.x;
         i < n4; i += stride) {
        float4 a = a4[i];
        float4 b = b4[i];
        float d0 = a.x - b.x;
        float d1 = a.y - b.y;
        float d2 = a.z - b.z;
        float d3 = a.w - b.w;
        acc = fmaf(d0, d0, acc);
        acc = fmaf(d1, d1, acc);
        acc = fmaf(d2, d2, acc);
        acc = fmaf(d3, d3, acc);
    }

    __shared__ float warp_sums[NTHR / 32];
    float bsum = block_reduce(acc, warp_sums);
    if (threadIdx.x == 0) g_partials[blockIdx.x] = bsum;

    // Fused finalization: last CTA to finish reduces all partials in a
    // fixed order (deterministic). Counter self-resets for graph replay.
    __shared__ bool s_last;
    __threadfence();
    if (threadIdx.x == 0) {
        unsigned int prev = atomicAdd(&g_done_count, 1u);
        s_last = (prev == NBLK - 1);
    }
    __syncthreads();

    if (s_last) {
        // 8192 partials / 256 threads = 32 each, fixed order => deterministic.
        float facc = 0.0f;
        #pragma unroll
        for (int k = 0; k < NBLK / NTHR; k++)
            facc += g_partials[threadIdx.x + k * NTHR];

        __syncthreads();  // warp_sums reuse
        float fsum = block_reduce(facc, warp_sums);
        if (threadIdx.x == 0) {
            out[0] = fsum * inv_n;
            g_done_count = 0;  // reset for next graph replay
        }
    }
}

extern "C" void kernel_launch(void* const* d_in, const int* in_sizes, int n_in,
                              void* d_out, int out_size)
{
    const float* yhat = (const float*)d_in[0];
    const float* y    = (const float*)d_in[1];
    float* out        = (float*)d_out;

    long long n  = (long long)in_sizes[0];  // 67108864, divisible by 4
    long long n4 = n / 4;

    mse_kernel<<<NBLK, NTHR>>>(yhat, y, out, n4, 1.0f / (float)n);
}

// round 10
// speedup vs baseline: 1.0036x; 1.0036x over previous
#include <cuda_runtime.h>

// ---------------------------------------------------------------------------
// MSELoss: out[0] = mean((yhat - y)^2) over 16384 x 4096 fp32 (512 MiB read).
// FINAL champion (best measured: 80.4 us wall, 85.3% DRAM, 6.76 TB/s ~ B300
// practical streaming ceiling):
//   - 2048 CTAs x 256 threads, plain compiler-scheduled float4 grid-stride.
//   - Fused deterministic last-block-done finalization: fixed-order partial
//     reduction (no float atomics), single launch, counter self-resets for
//     CUDA-graph replay.
//
// Exhaustively probed and rejected with measurements:
//   - manual 4-stride unroll        90.1 us (wrecked access pattern)
//   - __ldcs streaming loads        83.4 us (+6 regs, occ 95.6 -> 71.9)
//   - grid 1024x256                 (per-SM imbalance, occ 69%)
//   - grid 1184 (full wave)         80.6 us, DRAM -2.6% (neutral)
//   - 1024x512 (same thread count)  80.6 us (tie)
//   - 8192x256 (fine granularity)   80.6 us wall / 83.1 profiled (tie/worse)
// All shapes plateau at ~85% of spec => machine streaming ceiling reached.
// ---------------------------------------------------------------------------

#define NBLK 2048
#define NTHR 256

__device__ float        g_partials[NBLK];
__device__ unsigned int g_done_count = 0;

__device__ __forceinline__ float block_reduce(float acc, float* warp_sums)
{
    #pragma unroll
    for (int off = 16; off > 0; off >>= 1)
        acc += __shfl_xor_sync(0xFFFFFFFFu, acc, off);

    int lane = threadIdx.x & 31;
    int wid  = threadIdx.x >> 5;
    if (lane == 0) warp_sums[wid] = acc;
    __syncthreads();

    float v = 0.0f;
    if (wid == 0) {
        v = (lane < NTHR / 32) ? warp_sums[lane] : 0.0f;
        #pragma unroll
        for (int off = 16; off > 0; off >>= 1)
            v += __shfl_xor_sync(0xFFFFFFFFu, v, off);
    }
    return v;  // valid in warp 0 lane 0
}

__global__ __launch_bounds__(NTHR) void mse_kernel(
    const float* __restrict__ yhat,
    const float* __restrict__ y,
    float* __restrict__ out,
    long long n4, float inv_n)
{
    const float4* __restrict__ a4 = reinterpret_cast<const float4*>(yhat);
    const float4* __restrict__ b4 = reinterpret_cast<const float4*>(y);

    // Plain grid-stride loop, compiler-scheduled (best-measured shape).
    float acc = 0.0f;
    long long stride = (long long)gridDim.x * blockDim.x;
    for (long long i = (long long)blockIdx.x * blockDim.x + threadIdx.x;
         i < n4; i += stride) {
        float4 a = a4[i];
        float4 b = b4[i];
        float d0 = a.x - b.x;
        float d1 = a.y - b.y;
        float d2 = a.z - b.z;
        float d3 = a.w - b.w;
        acc = fmaf(d0, d0, acc);
        acc = fmaf(d1, d1, acc);
        acc = fmaf(d2, d2, acc);
        acc = fmaf(d3, d3, acc);
    }

    __shared__ float warp_sums[NTHR / 32];
    float bsum = block_reduce(acc, warp_sums);
    if (threadIdx.x == 0) g_partials[blockIdx.x] = bsum;

    // Fused finalization: last CTA to finish reduces all partials in a
    // fixed order (deterministic). Counter self-resets for graph replay.
    __shared__ bool s_last;
    __threadfence();
    if (threadIdx.x == 0) {
        unsigned int prev = atomicAdd(&g_done_count, 1u);
        s_last = (prev == NBLK - 1);
    }
    __syncthreads();

    if (s_last) {
        // 2048 partials / 256 threads = 8 each, fixed order => deterministic.
        float facc = 0.0f;
        #pragma unroll
        for (int k = 0; k < NBLK / NTHR; k++)
            facc += g_partials[threadIdx.x + k * NTHR];

        __syncthreads();  // warp_sums reuse
        float fsum = block_reduce(facc, warp_sums);
        if (threadIdx.x == 0) {
            out[0] = fsum * inv_n;
            g_done_count = 0;  // reset for next graph replay
        }
    }
}

extern "C" void kernel_launch(void* const* d_in, const int* in_sizes, int n_in,
                              void* d_out, int out_size)
{
    const float* yhat = (const float*)d_in[0];
    const float* y    = (const float*)d_in[1];
    float* out        = (float*)d_out;

    long long n  = (long long)in_sizes[0];  // 67108864, divisible by 4
    long long n4 = n / 4;

    mse_kernel<<<NBLK, NTHR>>>(yhat, y, out, n4, 1.0f / (float)n);
}